// round 1
// baseline (speedup 1.0000x reference)
#include <cuda_runtime.h>
#include <cstdint>

// sbvr decode:
//   out[g*16 + l] = sum_s coeff_cache[coeff_idx[g]][s] * ((bvr[g][s] >> l) & 1)
// G = 4,194,304 groups, S = 4 sums, L = 16 elements/group.
//
// Mapping: thread t handles group g = t>>2, elements [(t&3)*4, (t&3)*4+4).
// Output float4 index == t exactly (16 floats/group, 4 floats/thread).
// Select-based accumulation (LOP3.pred + FSEL + FADD) instead of
// bit-extract + I2F + FFMA to minimize issue pressure.

static constexpr unsigned NUM_THREADS_TOTAL = 16u * 1024u * 1024u;  // 4M groups * 4
static constexpr int BLOCK = 256;

__global__ __launch_bounds__(BLOCK) void sbvr_kernel(
    const float4* __restrict__ coeff_cache,   // [65536] rows of 4 floats
    const int*    __restrict__ coeff_idx,     // [G]
    const int4*   __restrict__ bvr,           // [G] (4 packed 16-bit words in int32)
    float4*       __restrict__ out)           // [4*G] float4 (= [G*16] floats)
{
    unsigned t = blockIdx.x * (unsigned)BLOCK + threadIdx.x;
    unsigned g = t >> 2;

    int ci  = __ldg(coeff_idx + g);       // issue early: gather depends on it
    int4 w  = __ldg(bvr + g);             // 4 lanes share address -> HW broadcast
    float4 c = __ldg(coeff_cache + ci);   // L2-resident 1MB table

    unsigned sub = (t & 3u) * 4u;
    unsigned m0 = 1u << sub;
    unsigned m1 = m0 << 1;
    unsigned m2 = m0 << 2;
    unsigned m3 = m0 << 3;

    float4 r;
    r.x = ((w.x & m0) ? c.x : 0.0f) + ((w.y & m0) ? c.y : 0.0f)
        + ((w.z & m0) ? c.z : 0.0f) + ((w.w & m0) ? c.w : 0.0f);
    r.y = ((w.x & m1) ? c.x : 0.0f) + ((w.y & m1) ? c.y : 0.0f)
        + ((w.z & m1) ? c.z : 0.0f) + ((w.w & m1) ? c.w : 0.0f);
    r.z = ((w.x & m2) ? c.x : 0.0f) + ((w.y & m2) ? c.y : 0.0f)
        + ((w.z & m2) ? c.z : 0.0f) + ((w.w & m2) ? c.w : 0.0f);
    r.w = ((w.x & m3) ? c.x : 0.0f) + ((w.y & m3) ? c.y : 0.0f)
        + ((w.z & m3) ? c.z : 0.0f) + ((w.w & m3) ? c.w : 0.0f);

    out[t] = r;
}

extern "C" void kernel_launch(void* const* d_in, const int* in_sizes, int n_in,
                              void* d_out, int out_size)
{
    const float4* coeff_cache = (const float4*)d_in[0];  // [65536,4] f32
    const int*    coeff_idx   = (const int*)d_in[1];     // [G] i32
    const int4*   bvr         = (const int4*)d_in[2];    // [G,4] i32
    float4*       out         = (float4*)d_out;          // [8192,8192] f32

    (void)in_sizes; (void)n_in; (void)out_size;

    unsigned blocks = NUM_THREADS_TOTAL / BLOCK;  // 65536
    sbvr_kernel<<<blocks, BLOCK>>>(coeff_cache, coeff_idx, bvr, out);
}

// round 2
// speedup vs baseline: 1.1237x; 1.1237x over previous
#include <cuda_runtime.h>
#include <cstdint>

// sbvr decode:
//   out[g*16 + l] = sum_s coeff_cache[coeff_idx[g]][s] * ((bvr[g][s] >> l) & 1)
// G = 4,194,304 groups, S = 4, L = 16.
//
// R1 -> R2 change: each thread now owns TWO quarter-groups, 8M apart, giving
// two independent idx->coeff dependency chains (MLP=2) to cover the ~1100cyc
// gather latency that left every pipe at ~50% in R1.
// Cache policy: __ldcs on single-use streams, __stcs on the 256MB output,
// __ldg keeps the 1MB coeff table cache-resident.

static constexpr unsigned QT_TOTAL = 16u * 1024u * 1024u;  // quarter-groups (4M groups * 4)
static constexpr unsigned QT_HALF  = QT_TOTAL / 2u;        // 8M
static constexpr int BLOCK = 256;

__device__ __forceinline__ float4 decode_quarter(int4 w, float4 c, unsigned m0)
{
    unsigned m1 = m0 << 1, m2 = m0 << 2, m3 = m0 << 3;
    float4 r;
    r.x = ((w.x & m0) ? c.x : 0.0f) + ((w.y & m0) ? c.y : 0.0f)
        + ((w.z & m0) ? c.z : 0.0f) + ((w.w & m0) ? c.w : 0.0f);
    r.y = ((w.x & m1) ? c.x : 0.0f) + ((w.y & m1) ? c.y : 0.0f)
        + ((w.z & m1) ? c.z : 0.0f) + ((w.w & m1) ? c.w : 0.0f);
    r.z = ((w.x & m2) ? c.x : 0.0f) + ((w.y & m2) ? c.y : 0.0f)
        + ((w.z & m2) ? c.z : 0.0f) + ((w.w & m2) ? c.w : 0.0f);
    r.w = ((w.x & m3) ? c.x : 0.0f) + ((w.y & m3) ? c.y : 0.0f)
        + ((w.z & m3) ? c.z : 0.0f) + ((w.w & m3) ? c.w : 0.0f);
    return r;
}

__global__ __launch_bounds__(BLOCK) void sbvr_kernel(
    const float4* __restrict__ coeff_cache,   // [65536] rows of 4 floats
    const int*    __restrict__ coeff_idx,     // [G]
    const int4*   __restrict__ bvr,           // [G]
    float4*       __restrict__ out)           // [4*G]
{
    unsigned t0 = blockIdx.x * (unsigned)BLOCK + threadIdx.x;
    unsigned t1 = t0 + QT_HALF;               // same (t&3), masks shared
    unsigned g0 = t0 >> 2;
    unsigned g1 = t1 >> 2;

    // Issue both independent chains' loads back-to-back (MLP=2).
    int ci0 = __ldcs(coeff_idx + g0);
    int ci1 = __ldcs(coeff_idx + g1);
    int4 w0 = __ldcs(bvr + g0);
    int4 w1 = __ldcs(bvr + g1);
    float4 c0 = __ldg(coeff_cache + ci0);
    float4 c1 = __ldg(coeff_cache + ci1);

    unsigned m0 = 1u << ((t0 & 3u) * 4u);

    float4 r0 = decode_quarter(w0, c0, m0);
    float4 r1 = decode_quarter(w1, c1, m0);

    __stcs(out + t0, r0);
    __stcs(out + t1, r1);
}

extern "C" void kernel_launch(void* const* d_in, const int* in_sizes, int n_in,
                              void* d_out, int out_size)
{
    const float4* coeff_cache = (const float4*)d_in[0];  // [65536,4] f32
    const int*    coeff_idx   = (const int*)d_in[1];     // [G] i32
    const int4*   bvr         = (const int4*)d_in[2];    // [G,4] i32
    float4*       out         = (float4*)d_out;          // [8192,8192] f32

    (void)in_sizes; (void)n_in; (void)out_size;

    unsigned blocks = QT_HALF / BLOCK;  // 32768 blocks of 256 threads
    sbvr_kernel<<<blocks, BLOCK>>>(coeff_cache, coeff_idx, bvr, out);
}

// round 3
// speedup vs baseline: 1.1301x; 1.0057x over previous
#include <cuda_runtime.h>
#include <cstdint>

// sbvr decode:
//   out[g*16 + l] = sum_s coeff_cache[coeff_idx[g]][s] * ((bvr[g][s] >> l) & 1)
// G = 4,194,304 groups, S = 4, L = 16.
//
// R2 -> R3:
//  * MLP=4: each thread owns FOUR quarter-groups (strides of 4M), four
//    independent idx->coeff gather chains to cover ~1100cyc latency.
//  * Pipe-balanced decode in inline PTX: lop3-with-predicate-output (1 ALU op
//    = AND + test) feeding a predicated add.f32 (FMA pipe). Replaces the
//    LOP3+FSEL all-ALU chain that left FMA at 14.7% while ALU hit 50.7%.
//    ptxas never emits bare @p adds from C++ if{} (BSSY/BSYNC wrap), hence asm.

static constexpr unsigned QT_TOTAL  = 16u * 1024u * 1024u;  // 4M groups * 4 quarters
static constexpr unsigned QT_STRIDE = QT_TOTAL / 4u;        // 4M
static constexpr int BLOCK = 256;

__device__ __forceinline__ float4 decode_quarter(int4 w, float4 c, unsigned m0)
{
    float4 r;
    asm(
    "{\n\t"
    ".reg .pred q, p0, p1, p2, p3;\n\t"
    ".reg .b32  t, m1, m2, m3;\n\t"
    "setp.ne.u32 q, %4, %4;\n\t"              // q = false (lop3 BoolOp sink)
    "shl.b32 m1, %8, 1;\n\t"
    "shl.b32 m2, %8, 2;\n\t"
    "shl.b32 m3, %8, 3;\n\t"
    // ---- element 0 (mask %8) ----
    "lop3.or.b32 t|p0, %4, %8, %4, 0xC0, q;\n\t"
    "lop3.or.b32 t|p1, %5, %8, %5, 0xC0, q;\n\t"
    "lop3.or.b32 t|p2, %6, %8, %6, 0xC0, q;\n\t"
    "lop3.or.b32 t|p3, %7, %8, %7, 0xC0, q;\n\t"
    "selp.f32 %0, %9, 0f00000000, p0;\n\t"
    "@p1 add.rn.f32 %0, %0, %10;\n\t"
    "@p2 add.rn.f32 %0, %0, %11;\n\t"
    "@p3 add.rn.f32 %0, %0, %12;\n\t"
    // ---- element 1 (mask m1) ----
    "lop3.or.b32 t|p0, %4, m1, %4, 0xC0, q;\n\t"
    "lop3.or.b32 t|p1, %5, m1, %5, 0xC0, q;\n\t"
    "lop3.or.b32 t|p2, %6, m1, %6, 0xC0, q;\n\t"
    "lop3.or.b32 t|p3, %7, m1, %7, 0xC0, q;\n\t"
    "selp.f32 %1, %9, 0f00000000, p0;\n\t"
    "@p1 add.rn.f32 %1, %1, %10;\n\t"
    "@p2 add.rn.f32 %1, %1, %11;\n\t"
    "@p3 add.rn.f32 %1, %1, %12;\n\t"
    // ---- element 2 (mask m2) ----
    "lop3.or.b32 t|p0, %4, m2, %4, 0xC0, q;\n\t"
    "lop3.or.b32 t|p1, %5, m2, %5, 0xC0, q;\n\t"
    "lop3.or.b32 t|p2, %6, m2, %6, 0xC0, q;\n\t"
    "lop3.or.b32 t|p3, %7, m2, %7, 0xC0, q;\n\t"
    "selp.f32 %2, %9, 0f00000000, p0;\n\t"
    "@p1 add.rn.f32 %2, %2, %10;\n\t"
    "@p2 add.rn.f32 %2, %2, %11;\n\t"
    "@p3 add.rn.f32 %2, %2, %12;\n\t"
    // ---- element 3 (mask m3) ----
    "lop3.or.b32 t|p0, %4, m3, %4, 0xC0, q;\n\t"
    "lop3.or.b32 t|p1, %5, m3, %5, 0xC0, q;\n\t"
    "lop3.or.b32 t|p2, %6, m3, %6, 0xC0, q;\n\t"
    "lop3.or.b32 t|p3, %7, m3, %7, 0xC0, q;\n\t"
    "selp.f32 %3, %9, 0f00000000, p0;\n\t"
    "@p1 add.rn.f32 %3, %3, %10;\n\t"
    "@p2 add.rn.f32 %3, %3, %11;\n\t"
    "@p3 add.rn.f32 %3, %3, %12;\n\t"
    "}\n\t"
    : "=f"(r.x), "=f"(r.y), "=f"(r.z), "=f"(r.w)
    : "r"(w.x), "r"(w.y), "r"(w.z), "r"(w.w),
      "r"(m0),
      "f"(c.x), "f"(c.y), "f"(c.z), "f"(c.w));
    return r;
}

__global__ __launch_bounds__(BLOCK) void sbvr_kernel(
    const float4* __restrict__ coeff_cache,   // [65536] rows of 4 floats
    const int*    __restrict__ coeff_idx,     // [G]
    const int4*   __restrict__ bvr,           // [G]
    float4*       __restrict__ out)           // [4*G]
{
    unsigned t0 = blockIdx.x * (unsigned)BLOCK + threadIdx.x;
    unsigned t1 = t0 + QT_STRIDE;
    unsigned t2 = t1 + QT_STRIDE;
    unsigned t3 = t2 + QT_STRIDE;

    // Four independent gather chains, loads issued back-to-back (MLP=4).
    int ci0 = __ldcs(coeff_idx + (t0 >> 2));
    int ci1 = __ldcs(coeff_idx + (t1 >> 2));
    int ci2 = __ldcs(coeff_idx + (t2 >> 2));
    int ci3 = __ldcs(coeff_idx + (t3 >> 2));
    int4 w0 = __ldcs(bvr + (t0 >> 2));
    int4 w1 = __ldcs(bvr + (t1 >> 2));
    int4 w2 = __ldcs(bvr + (t2 >> 2));
    int4 w3 = __ldcs(bvr + (t3 >> 2));
    float4 c0 = __ldg(coeff_cache + ci0);
    float4 c1 = __ldg(coeff_cache + ci1);
    float4 c2 = __ldg(coeff_cache + ci2);
    float4 c3 = __ldg(coeff_cache + ci3);

    unsigned m0 = 1u << ((t0 & 3u) * 4u);  // same for t1..t3 (stride % 4 == 0)

    __stcs(out + t0, decode_quarter(w0, c0, m0));
    __stcs(out + t1, decode_quarter(w1, c1, m0));
    __stcs(out + t2, decode_quarter(w2, c2, m0));
    __stcs(out + t3, decode_quarter(w3, c3, m0));
}

extern "C" void kernel_launch(void* const* d_in, const int* in_sizes, int n_in,
                              void* d_out, int out_size)
{
    const float4* coeff_cache = (const float4*)d_in[0];  // [65536,4] f32
    const int*    coeff_idx   = (const int*)d_in[1];     // [G] i32
    const int4*   bvr         = (const int4*)d_in[2];    // [G,4] i32
    float4*       out         = (float4*)d_out;          // [8192,8192] f32

    (void)in_sizes; (void)n_in; (void)out_size;

    unsigned blocks = QT_STRIDE / BLOCK;  // 16384
    sbvr_kernel<<<blocks, BLOCK>>>(coeff_cache, coeff_idx, bvr, out);
}